// round 15
// baseline (speedup 1.0000x reference)
#include <cuda_runtime.h>
#include <cuda_bf16.h>
#include <math.h>
#include <stdint.h>

#define NN 80000
#define EE 1280000
#define DOUT_FINAL 40
#define BKT 64       // bucket capacity per node (deg ~ Poisson(16); P(>=64) ~ 1e-22)
#define STRIDE 136   // smem row stride in bf16 elems

// ---------------- scratch (static device globals; no allocs) ----------------
__device__ __nv_bfloat16 g_bfA[(size_t)NN * 64];
__device__ __nv_bfloat16 g_bfB[(size_t)NN * 64];
__device__ __nv_bfloat16 g_aggr[(size_t)NN * 64];  // per-layer mean aggregation
__device__ __nv_bfloat16 g_wbf[3][64 * 128];   // stacked [Wl^T;Wr^T] as [n][k]
__device__ float g_bias[3][64];
__device__ int   g_cursor[NN];                 // per-node fill count (== degree)
__device__ int   g_bkt[(size_t)NN * BKT];      // neighbor buckets
__device__ float g_acc[2];
__device__ int   g_done;

// ---------------- preamble (2 kernels) ----------------
__global__ void k_zero(const float* __restrict__ Wl0, const float* __restrict__ bl0,
                       const float* __restrict__ Wr0, const float* __restrict__ br0,
                       const float* __restrict__ Wl1, const float* __restrict__ bl1,
                       const float* __restrict__ Wr1, const float* __restrict__ br1,
                       const float* __restrict__ Wl2, const float* __restrict__ bl2,
                       const float* __restrict__ Wr2, const float* __restrict__ br2) {
    int i = blockIdx.x * blockDim.x + threadIdx.x;   // 80,128 threads
    if (i < NN) g_cursor[i] = 0;
    if (i < 2)  g_acc[i] = 0.f;
    if (i == 2) g_done = 0;
    if (i < 3 * 64 * 128) {
        int l = i >> 13, r = i & 8191, n = r >> 7, k = r & 127;
        float w = 0.f;
        if (l == 0)      w = (k < 64) ? __ldg(Wl0 + n * 64 + k) : __ldg(Wr0 + n * 64 + k - 64);
        else if (l == 1) w = (k < 64) ? __ldg(Wl1 + n * 64 + k) : __ldg(Wr1 + n * 64 + k - 64);
        else if (n < DOUT_FINAL)
                         w = (k < 64) ? __ldg(Wl2 + n * 64 + k) : __ldg(Wr2 + n * 64 + k - 64);
        g_wbf[l][n * 128 + k] = __float2bfloat16(w);
    }
    if (i < 3 * 64) {
        int l = i >> 6, n = i & 63;
        float b = 0.f;
        if (l == 0)      b = __ldg(bl0 + n) + __ldg(br0 + n);
        else if (l == 1) b = __ldg(bl1 + n) + __ldg(br1 + n);
        else if (n < DOUT_FINAL) b = __ldg(bl2 + n) + __ldg(br2 + n);
        g_bias[l][n] = b;
    }
}

// fused: direct bucket scatter (4 edges/thread) + x -> bf16 (4 chunks/thread)
__global__ void k_build(const int* __restrict__ dst, const int* __restrict__ src,
                        const float* __restrict__ x) {
    int i = blockIdx.x * blockDim.x + threadIdx.x;   // 320,000 threads
    if (i < EE / 4) {
        int4 d = __ldg((const int4*)dst + i);
        int4 s = __ldg((const int4*)src + i);
        int c0 = atomicAdd(&g_cursor[d.x], 1);
        if (c0 < BKT) g_bkt[(size_t)d.x * BKT + c0] = s.x;
        int c1 = atomicAdd(&g_cursor[d.y], 1);
        if (c1 < BKT) g_bkt[(size_t)d.y * BKT + c1] = s.y;
        int c2 = atomicAdd(&g_cursor[d.z], 1);
        if (c2 < BKT) g_bkt[(size_t)d.z * BKT + c2] = s.z;
        int c3 = atomicAdd(&g_cursor[d.w], 1);
        if (c3 < BKT) g_bkt[(size_t)d.w * BKT + c3] = s.w;
    }
    #pragma unroll
    for (int r = 0; r < 4; ++r) {
        int c = i * 4 + r;                           // < NN*16 == 1,280,000
        float4 v = __ldg((const float4*)x + c);
        __nv_bfloat162 a = __floats2bfloat162_rn(v.x, v.y);
        __nv_bfloat162 b = __floats2bfloat162_rn(v.z, v.w);
        uint2 u;
        u.x = *(unsigned*)&a; u.y = *(unsigned*)&b;
        ((uint2*)g_bfA)[c] = u;
    }
}

// ---------------- helpers ----------------
__device__ __forceinline__ void add8(float* a, uint4 u) {
    a[0] += __uint_as_float(u.x << 16);
    a[1] += __uint_as_float(u.x & 0xFFFF0000u);
    a[2] += __uint_as_float(u.y << 16);
    a[3] += __uint_as_float(u.y & 0xFFFF0000u);
    a[4] += __uint_as_float(u.z << 16);
    a[5] += __uint_as_float(u.z & 0xFFFF0000u);
    a[6] += __uint_as_float(u.w << 16);
    a[7] += __uint_as_float(u.w & 0xFFFF0000u);
}

__device__ __forceinline__ uint4 badd(uint4 a, uint4 b) {
    uint4 r;
    *(__nv_bfloat162*)&r.x = __hadd2(*(const __nv_bfloat162*)&a.x, *(const __nv_bfloat162*)&b.x);
    *(__nv_bfloat162*)&r.y = __hadd2(*(const __nv_bfloat162*)&a.y, *(const __nv_bfloat162*)&b.y);
    *(__nv_bfloat162*)&r.z = __hadd2(*(const __nv_bfloat162*)&a.z, *(const __nv_bfloat162*)&b.z);
    *(__nv_bfloat162*)&r.w = __hadd2(*(const __nv_bfloat162*)&a.w, *(const __nv_bfloat162*)&b.w);
    return r;
}

__device__ __forceinline__ void mma16816(float& c0, float& c1, float& c2, float& c3,
                                         uint32_t a0, uint32_t a1, uint32_t a2, uint32_t a3,
                                         uint32_t b0, uint32_t b1) {
    asm volatile("mma.sync.aligned.m16n8k16.row.col.f32.bf16.bf16.f32 "
                 "{%0,%1,%2,%3}, {%4,%5,%6,%7}, {%8,%9}, {%0,%1,%2,%3};"
                 : "+f"(c0), "+f"(c1), "+f"(c2), "+f"(c3)
                 : "r"(a0), "r"(a1), "r"(a2), "r"(a3), "r"(b0), "r"(b1));
}

// ---------------- standalone gather: quarter-warp per node, no smem, no barriers
__global__ void __launch_bounds__(256) k_gather(const __nv_bfloat16* __restrict__ hbf) {
    int node = (blockIdx.x * 256 + threadIdx.x) >> 3;   // 2500 blocks -> 80,000 nodes
    if (node >= NN) return;
    const int d8 = threadIdx.x & 7;
    int dg = __ldg(g_cursor + node);
    int dgc = dg < BKT ? dg : BKT;
    const int* bp = g_bkt + (size_t)node * BKT;
    float a[8] = {0.f, 0.f, 0.f, 0.f, 0.f, 0.f, 0.f, 0.f};
    int j = 0;
    for (; j + 7 < dgc; j += 8) {
        int4 ia = __ldg((const int4*)(bp + j));
        int4 ib = __ldg((const int4*)(bp + j + 4));
        uint4 u0 = __ldg((const uint4*)(hbf + (size_t)ia.x * 64) + d8);
        uint4 u1 = __ldg((const uint4*)(hbf + (size_t)ia.y * 64) + d8);
        uint4 u2 = __ldg((const uint4*)(hbf + (size_t)ia.z * 64) + d8);
        uint4 u3 = __ldg((const uint4*)(hbf + (size_t)ia.w * 64) + d8);
        uint4 u4 = __ldg((const uint4*)(hbf + (size_t)ib.x * 64) + d8);
        uint4 u5 = __ldg((const uint4*)(hbf + (size_t)ib.y * 64) + d8);
        uint4 u6 = __ldg((const uint4*)(hbf + (size_t)ib.z * 64) + d8);
        uint4 u7 = __ldg((const uint4*)(hbf + (size_t)ib.w * 64) + d8);
        uint4 p0 = badd(badd(u0, u1), badd(u2, u3));
        uint4 p1 = badd(badd(u4, u5), badd(u6, u7));
        add8(a, p0);
        add8(a, p1);
    }
    for (; j + 3 < dgc; j += 4) {
        int4 ia = __ldg((const int4*)(bp + j));
        uint4 u0 = __ldg((const uint4*)(hbf + (size_t)ia.x * 64) + d8);
        uint4 u1 = __ldg((const uint4*)(hbf + (size_t)ia.y * 64) + d8);
        uint4 u2 = __ldg((const uint4*)(hbf + (size_t)ia.z * 64) + d8);
        uint4 u3 = __ldg((const uint4*)(hbf + (size_t)ia.w * 64) + d8);
        add8(a, badd(u0, u1));
        add8(a, badd(u2, u3));
    }
    for (; j < dgc; ++j) {
        int i0 = __ldg(bp + j);
        uint4 u0 = __ldg((const uint4*)(hbf + (size_t)i0 * 64) + d8);
        add8(a, u0);
    }
    float di = (dg > 0) ? 1.f / (float)dg : 0.f;
    __nv_bfloat162 p0 = __floats2bfloat162_rn(a[0] * di, a[1] * di);
    __nv_bfloat162 p1 = __floats2bfloat162_rn(a[2] * di, a[3] * di);
    __nv_bfloat162 p2 = __floats2bfloat162_rn(a[4] * di, a[5] * di);
    __nv_bfloat162 p3 = __floats2bfloat162_rn(a[6] * di, a[7] * di);
    uint4 u;
    u.x = *(unsigned*)&p0; u.y = *(unsigned*)&p1;
    u.z = *(unsigned*)&p2; u.w = *(unsigned*)&p3;
    *((uint4*)(g_aggr + (size_t)node * 64) + d8) = u;
}

// ---------------- transform: stage (aggr|self) + HMMA (+loss & final if LAST) ----
template<bool RELU, bool LAST>
__global__ void __launch_bounds__(256) k_transform(
    const __nv_bfloat16* __restrict__ hbf,
    const __nv_bfloat16* __restrict__ wbf,
    const float* __restrict__ bias,
    __nv_bfloat16* __restrict__ outbf,
    const int* __restrict__ y,
    const int* __restrict__ mask,
    float* __restrict__ out_final)
{
    __shared__ __nv_bfloat16 s_act[64 * STRIDE];  // [node][k]  k<64 aggr, k>=64 self
    __shared__ __nv_bfloat16 s_w[64 * STRIDE];    // [n][k]; reused as float logits in LAST
    __shared__ float s_b[64];

    const int t  = threadIdx.x;
    const int nb = blockIdx.x * 64;

    // stage weights
    #pragma unroll
    for (int idx = t; idx < 1024; idx += 256) {
        int n = idx >> 4, c = idx & 15;
        *(uint4*)(s_w + n * STRIDE + c * 8) = __ldg((const uint4*)(wbf + n * 128) + c);
    }
    if (t < 64) s_b[t] = __ldg(bias + t);

    // stage aggr (k<64) and self (k>=64), both coalesced
    #pragma unroll
    for (int idx = t; idx < 512; idx += 256) {
        int n = idx >> 3, c = idx & 7;
        *(uint4*)(s_act + n * STRIDE + c * 8) =
            __ldg((const uint4*)(g_aggr + (size_t)(nb + n) * 64) + c);
        *(uint4*)(s_act + n * STRIDE + 64 + c * 8) =
            __ldg((const uint4*)(hbf + (size_t)(nb + n) * 64) + c);
    }
    __syncthreads();

    // HMMA: warp -> m16 x n32 tile; 8 warps cover 64x64
    const int w    = t >> 5;
    const int lane = t & 31;
    const int mw = (w & 3) * 16;
    const int nw = (w >> 2) * 32;
    const int g  = lane >> 2;
    const int tg = lane & 3;

    float c[4][4];
    #pragma unroll
    for (int nt = 0; nt < 4; ++nt) {
        int n0 = nw + nt * 8 + 2 * tg;
        c[nt][0] = s_b[n0]; c[nt][1] = s_b[n0 + 1];
        c[nt][2] = c[nt][0]; c[nt][3] = c[nt][1];
    }

    #pragma unroll
    for (int kk = 0; kk < 8; ++kk) {
        int k0 = kk * 16;
        const __nv_bfloat16* pa = s_act + (mw + g) * STRIDE + k0 + 2 * tg;
        uint32_t a0 = *(const uint32_t*)pa;
        uint32_t a1 = *(const uint32_t*)(pa + 8 * STRIDE);
        uint32_t a2 = *(const uint32_t*)(pa + 8);
        uint32_t a3 = *(const uint32_t*)(pa + 8 * STRIDE + 8);
        #pragma unroll
        for (int nt = 0; nt < 4; ++nt) {
            const __nv_bfloat16* pb = s_w + (nw + nt * 8 + g) * STRIDE + k0 + 2 * tg;
            uint32_t b0 = *(const uint32_t*)pb;
            uint32_t b1 = *(const uint32_t*)(pb + 8);
            mma16816(c[nt][0], c[nt][1], c[nt][2], c[nt][3], a0, a1, a2, a3, b0, b1);
        }
    }

    if (!LAST) {
        #pragma unroll
        for (int nt = 0; nt < 4; ++nt) {
            int n0 = nw + nt * 8 + 2 * tg;
            int m0 = nb + mw + g;
            float v0 = c[nt][0], v1 = c[nt][1], v2 = c[nt][2], v3 = c[nt][3];
            if (RELU) {
                v0 = fmaxf(v0, 0.f); v1 = fmaxf(v1, 0.f);
                v2 = fmaxf(v2, 0.f); v3 = fmaxf(v3, 0.f);
            }
            __nv_bfloat162 p0 = __floats2bfloat162_rn(v0, v1);
            __nv_bfloat162 p1 = __floats2bfloat162_rn(v2, v3);
            *(__nv_bfloat162*)(outbf + (size_t)m0 * 64 + n0) = p0;
            *(__nv_bfloat162*)(outbf + (size_t)(m0 + 8) * 64 + n0) = p1;
        }
    } else {
        // logits -> smem (overlay dead weight tile), then fused loss + final
        __syncthreads();
        float* lf = (float*)s_w;               // [64][41] floats
        #pragma unroll
        for (int nt = 0; nt < 4; ++nt) {
            int n0 = nw + nt * 8 + 2 * tg;
            if (n0 < DOUT_FINAL) {
                lf[(mw + g) * 41 + n0]         = c[nt][0];
                lf[(mw + g) * 41 + n0 + 1]     = c[nt][1];
                lf[(mw + g + 8) * 41 + n0]     = c[nt][2];
                lf[(mw + g + 8) * 41 + n0 + 1] = c[nt][3];
            }
        }
        __syncthreads();
        if (t < 64) {
            float nll = 0.f, mv = 0.f;
            int gn = nb + t;
            if (__ldg(mask + gn) != 0) {
                const float* l = lf + t * 41;
                float mx = l[0];
                #pragma unroll
                for (int d = 1; d < DOUT_FINAL; ++d) mx = fmaxf(mx, l[d]);
                float s = 0.f;
                #pragma unroll
                for (int d = 0; d < DOUT_FINAL; ++d) s += expf(l[d] - mx);
                nll = mx + logf(s) - l[__ldg(y + gn)];
                mv = 1.f;
            }
            #pragma unroll
            for (int o = 16; o > 0; o >>= 1) {
                nll += __shfl_down_sync(0xffffffffu, nll, o);
                mv  += __shfl_down_sync(0xffffffffu, mv, o);
            }
            if ((t & 31) == 0) {
                atomicAdd(&g_acc[0], nll);
                atomicAdd(&g_acc[1], mv);
            }
        }
        __syncthreads();
        if (t == 0) {
            __threadfence();
            int n = atomicAdd(&g_done, 1);
            if (n == NN / 64 - 1) {
                out_final[0] = g_acc[0] / fmaxf(g_acc[1], 1.f);
            }
        }
    }
}

// ---------------- launcher ----------------
extern "C" void kernel_launch(void* const* d_in, const int* in_sizes, int n_in,
                              void* d_out, int out_size) {
    const float* x   = (const float*)d_in[0];
    const float* Wl0 = (const float*)d_in[1];
    const float* bl0 = (const float*)d_in[2];
    const float* Wr0 = (const float*)d_in[3];
    const float* br0 = (const float*)d_in[4];
    const float* Wl1 = (const float*)d_in[5];
    const float* bl1 = (const float*)d_in[6];
    const float* Wr1 = (const float*)d_in[7];
    const float* br1 = (const float*)d_in[8];
    const float* Wl2 = (const float*)d_in[9];
    const float* bl2 = (const float*)d_in[10];
    const float* Wr2 = (const float*)d_in[11];
    const float* br2 = (const float*)d_in[12];
    const int*   ei  = (const int*)d_in[13];
    const int*   y   = (const int*)d_in[14];
    const int*   msk = (const int*)d_in[15];
    const int* dst = ei;        // edge_index[0]
    const int* src = ei + EE;   // edge_index[1]

    __nv_bfloat16 *bfA, *bfB, *wbf;
    float *bias;
    cudaGetSymbolAddress((void**)&bfA, g_bfA);
    cudaGetSymbolAddress((void**)&bfB, g_bfB);
    cudaGetSymbolAddress((void**)&wbf, g_wbf);
    cudaGetSymbolAddress((void**)&bias, g_bias);

    // preamble
    k_zero<<<(NN + 255) / 256, 256>>>(Wl0, bl0, Wr0, br0, Wl1, bl1, Wr1, br1, Wl2, bl2, Wr2, br2);
    k_build<<<1250, 256>>>(dst, src, x);

    const int gblocks = (NN * 8 + 255) / 256;  // 2500
    const int tblocks = NN / 64;               // 1250

    // layer 0: bfA -> bfB
    k_gather<<<gblocks, 256>>>(bfA);
    k_transform<true, false><<<tblocks, 256>>>(bfA, wbf, bias, bfB, nullptr, nullptr, nullptr);
    // layer 1: bfB -> bfA
    k_gather<<<gblocks, 256>>>(bfB);
    k_transform<true, false><<<tblocks, 256>>>(bfB, wbf + 64 * 128, bias + 64, bfA, nullptr, nullptr, nullptr);
    // layer 2: bfA -> loss + final (fused)
    k_gather<<<gblocks, 256>>>(bfA);
    k_transform<false, true><<<tblocks, 256>>>(bfA, wbf + 2 * 64 * 128, bias + 128, nullptr, y, msk, (float*)d_out);
}

// round 16
// speedup vs baseline: 1.0530x; 1.0530x over previous
#include <cuda_runtime.h>
#include <cuda_bf16.h>
#include <math.h>
#include <stdint.h>

#define NN 80000
#define EE 1280000
#define DOUT_FINAL 40
#define BKT 64       // bucket capacity per node (deg ~ Poisson(16); P(>=64) ~ 1e-22)
#define STRIDE 136   // smem row stride in bf16 elems

// ---------------- scratch (static device globals; no allocs) ----------------
__device__ __nv_bfloat16 g_bfA[(size_t)NN * 64];
__device__ __nv_bfloat16 g_bfB[(size_t)NN * 64];
__device__ __nv_bfloat16 g_wbf[3][64 * 128];   // stacked [Wl^T;Wr^T] as [n][k]
__device__ float g_bias[3][64];
__device__ int   g_cursor[NN];                 // per-node fill count (== degree)
__device__ int   g_bkt[(size_t)NN * BKT];      // neighbor buckets
__device__ float g_acc[2];

// ---------------- preamble (2 kernels) ----------------
__global__ void k_zero(const float* __restrict__ Wl0, const float* __restrict__ bl0,
                       const float* __restrict__ Wr0, const float* __restrict__ br0,
                       const float* __restrict__ Wl1, const float* __restrict__ bl1,
                       const float* __restrict__ Wr1, const float* __restrict__ br1,
                       const float* __restrict__ Wl2, const float* __restrict__ bl2,
                       const float* __restrict__ Wr2, const float* __restrict__ br2) {
    int i = blockIdx.x * blockDim.x + threadIdx.x;   // 80,128 threads
    if (i < NN) g_cursor[i] = 0;
    if (i < 2)  g_acc[i] = 0.f;
    if (i < 3 * 64 * 128) {
        int l = i >> 13, r = i & 8191, n = r >> 7, k = r & 127;
        float w = 0.f;
        if (l == 0)      w = (k < 64) ? __ldg(Wl0 + n * 64 + k) : __ldg(Wr0 + n * 64 + k - 64);
        else if (l == 1) w = (k < 64) ? __ldg(Wl1 + n * 64 + k) : __ldg(Wr1 + n * 64 + k - 64);
        else if (n < DOUT_FINAL)
                         w = (k < 64) ? __ldg(Wl2 + n * 64 + k) : __ldg(Wr2 + n * 64 + k - 64);
        g_wbf[l][n * 128 + k] = __float2bfloat16(w);
    }
    if (i < 3 * 64) {
        int l = i >> 6, n = i & 63;
        float b = 0.f;
        if (l == 0)      b = __ldg(bl0 + n) + __ldg(br0 + n);
        else if (l == 1) b = __ldg(bl1 + n) + __ldg(br1 + n);
        else if (n < DOUT_FINAL) b = __ldg(bl2 + n) + __ldg(br2 + n);
        g_bias[l][n] = b;
    }
}

// fused: direct bucket scatter (4 edges/thread) + x -> bf16 (4 chunks/thread)
__global__ void k_build(const int* __restrict__ dst, const int* __restrict__ src,
                        const float* __restrict__ x) {
    int i = blockIdx.x * blockDim.x + threadIdx.x;   // 320,000 threads
    if (i < EE / 4) {
        int4 d = __ldg((const int4*)dst + i);
        int4 s = __ldg((const int4*)src + i);
        int c0 = atomicAdd(&g_cursor[d.x], 1);
        if (c0 < BKT) g_bkt[(size_t)d.x * BKT + c0] = s.x;
        int c1 = atomicAdd(&g_cursor[d.y], 1);
        if (c1 < BKT) g_bkt[(size_t)d.y * BKT + c1] = s.y;
        int c2 = atomicAdd(&g_cursor[d.z], 1);
        if (c2 < BKT) g_bkt[(size_t)d.z * BKT + c2] = s.z;
        int c3 = atomicAdd(&g_cursor[d.w], 1);
        if (c3 < BKT) g_bkt[(size_t)d.w * BKT + c3] = s.w;
    }
    #pragma unroll
    for (int r = 0; r < 4; ++r) {
        int c = i * 4 + r;                           // < NN*16 == 1,280,000
        float4 v = __ldg((const float4*)x + c);
        __nv_bfloat162 a = __floats2bfloat162_rn(v.x, v.y);
        __nv_bfloat162 b = __floats2bfloat162_rn(v.z, v.w);
        uint2 u;
        u.x = *(unsigned*)&a; u.y = *(unsigned*)&b;
        ((uint2*)g_bfA)[c] = u;
    }
}

// ---------------- fused layer: bf16 gather + HMMA transform (+loss if LAST) ----
// bf16 -> f32 widening is a 16-bit shift (same exponent width); stay on alu/fma pipes.
__device__ __forceinline__ void add8(float* a, uint4 u) {
    a[0] += __uint_as_float(u.x << 16);
    a[1] += __uint_as_float(u.x & 0xFFFF0000u);
    a[2] += __uint_as_float(u.y << 16);
    a[3] += __uint_as_float(u.y & 0xFFFF0000u);
    a[4] += __uint_as_float(u.z << 16);
    a[5] += __uint_as_float(u.z & 0xFFFF0000u);
    a[6] += __uint_as_float(u.w << 16);
    a[7] += __uint_as_float(u.w & 0xFFFF0000u);
}

// packed bf16x2 add of two rows (HADD2 x4)
__device__ __forceinline__ uint4 badd(uint4 a, uint4 b) {
    uint4 r;
    *(__nv_bfloat162*)&r.x = __hadd2(*(const __nv_bfloat162*)&a.x, *(const __nv_bfloat162*)&b.x);
    *(__nv_bfloat162*)&r.y = __hadd2(*(const __nv_bfloat162*)&a.y, *(const __nv_bfloat162*)&b.y);
    *(__nv_bfloat162*)&r.z = __hadd2(*(const __nv_bfloat162*)&a.z, *(const __nv_bfloat162*)&b.z);
    *(__nv_bfloat162*)&r.w = __hadd2(*(const __nv_bfloat162*)&a.w, *(const __nv_bfloat162*)&b.w);
    return r;
}

__device__ __forceinline__ void mma16816(float& c0, float& c1, float& c2, float& c3,
                                         uint32_t a0, uint32_t a1, uint32_t a2, uint32_t a3,
                                         uint32_t b0, uint32_t b1) {
    asm volatile("mma.sync.aligned.m16n8k16.row.col.f32.bf16.bf16.f32 "
                 "{%0,%1,%2,%3}, {%4,%5,%6,%7}, {%8,%9}, {%0,%1,%2,%3};"
                 : "+f"(c0), "+f"(c1), "+f"(c2), "+f"(c3)
                 : "r"(a0), "r"(a1), "r"(a2), "r"(a3), "r"(b0), "r"(b1));
}

template<bool RELU, bool LAST>
__global__ void __launch_bounds__(256) k_layer(
    const __nv_bfloat16* __restrict__ hbf,   // input activations (bf16)
    const __nv_bfloat16* __restrict__ wbf,   // [64][128] stacked weights
    const float* __restrict__ bias,          // [64] bl+br
    __nv_bfloat16* __restrict__ outbf,       // next-layer activations (if !LAST)
    const int* __restrict__ y,               // labels (if LAST)
    const int* __restrict__ mask)            // train mask (if LAST)
{
    __shared__ __nv_bfloat16 s_act[64 * STRIDE];  // [node][k]  k<64 aggr, k>=64 self
    __shared__ __nv_bfloat16 s_w[64 * STRIDE];    // [n][k]; reused as float logits in LAST
    __shared__ float s_b[64];

    const int t  = threadIdx.x;
    const int nb = blockIdx.x * 64;

    // stage weights (uint4 = 8 bf16)
    #pragma unroll
    for (int idx = t; idx < 1024; idx += 256) {
        int n = idx >> 4, c = idx & 15;
        *(uint4*)(s_w + n * STRIDE + c * 8) = __ldg((const uint4*)(wbf + n * 128) + c);
    }
    if (t < 64) s_b[t] = __ldg(bias + t);

    // stage self rows into k = 64..127
    #pragma unroll
    for (int idx = t; idx < 512; idx += 256) {
        int n = idx >> 3, c = idx & 7;
        *(uint4*)(s_act + n * STRIDE + 64 + c * 8) =
            __ldg((const uint4*)(hbf + (size_t)(nb + n) * 64) + c);
    }

    // gather: quarter-warp owns one node (4 independent chains/warp), 2 rounds,
    // int4 index loads + 8-deep row batching + bf16 pairwise-tree reduction.
    // In LAST layer, unmasked nodes are skipped (their logits are never read).
    {
        const int w    = t >> 5;
        const int q    = (t & 31) >> 3;   // quarter index -> which node this round
        const int d8   = t & 7;           // 16B chunk of the 128B row
        #pragma unroll
        for (int rd = 0; rd < 2; ++rd) {
            int nl = w * 8 + rd * 4 + q;
            int gn = nb + nl;
            if (LAST && __ldg(mask + gn) == 0) continue;   // loss never reads this row
            int dg = __ldg(g_cursor + gn);
            int dgc = dg < BKT ? dg : BKT;
            const int* bp = g_bkt + (size_t)gn * BKT;
            float a[8] = {0.f, 0.f, 0.f, 0.f, 0.f, 0.f, 0.f, 0.f};
            int j = 0;
            for (; j + 7 < dgc; j += 8) {
                int4 ia = __ldg((const int4*)(bp + j));
                int4 ib = __ldg((const int4*)(bp + j + 4));
                uint4 u0 = __ldg((const uint4*)(hbf + (size_t)ia.x * 64) + d8);
                uint4 u1 = __ldg((const uint4*)(hbf + (size_t)ia.y * 64) + d8);
                uint4 u2 = __ldg((const uint4*)(hbf + (size_t)ia.z * 64) + d8);
                uint4 u3 = __ldg((const uint4*)(hbf + (size_t)ia.w * 64) + d8);
                uint4 u4 = __ldg((const uint4*)(hbf + (size_t)ib.x * 64) + d8);
                uint4 u5 = __ldg((const uint4*)(hbf + (size_t)ib.y * 64) + d8);
                uint4 u6 = __ldg((const uint4*)(hbf + (size_t)ib.z * 64) + d8);
                uint4 u7 = __ldg((const uint4*)(hbf + (size_t)ib.w * 64) + d8);
                uint4 p0 = badd(badd(u0, u1), badd(u2, u3));
                uint4 p1 = badd(badd(u4, u5), badd(u6, u7));
                add8(a, p0);
                add8(a, p1);
            }
            for (; j + 3 < dgc; j += 4) {
                int4 ia = __ldg((const int4*)(bp + j));
                uint4 u0 = __ldg((const uint4*)(hbf + (size_t)ia.x * 64) + d8);
                uint4 u1 = __ldg((const uint4*)(hbf + (size_t)ia.y * 64) + d8);
                uint4 u2 = __ldg((const uint4*)(hbf + (size_t)ia.z * 64) + d8);
                uint4 u3 = __ldg((const uint4*)(hbf + (size_t)ia.w * 64) + d8);
                add8(a, badd(u0, u1));
                add8(a, badd(u2, u3));
            }
            for (; j < dgc; ++j) {
                int i0 = __ldg(bp + j);
                uint4 u0 = __ldg((const uint4*)(hbf + (size_t)i0 * 64) + d8);
                add8(a, u0);
            }
            float di = (dg > 0) ? 1.f / (float)dg : 0.f;
            __nv_bfloat162 p0 = __floats2bfloat162_rn(a[0] * di, a[1] * di);
            __nv_bfloat162 p1 = __floats2bfloat162_rn(a[2] * di, a[3] * di);
            __nv_bfloat162 p2 = __floats2bfloat162_rn(a[4] * di, a[5] * di);
            __nv_bfloat162 p3 = __floats2bfloat162_rn(a[6] * di, a[7] * di);
            uint4 u;
            u.x = *(unsigned*)&p0; u.y = *(unsigned*)&p1;
            u.z = *(unsigned*)&p2; u.w = *(unsigned*)&p3;
            *(uint4*)(s_act + nl * STRIDE + d8 * 8) = u;
        }
    }
    __syncthreads();

    // HMMA: warp -> m16 x n32 tile; 8 warps cover 64x64
    {
        const int w    = t >> 5;
        const int lane = t & 31;
        const int mw = (w & 3) * 16;
        const int nw = (w >> 2) * 32;
        const int g  = lane >> 2;
        const int tg = lane & 3;

        float c[4][4];
        #pragma unroll
        for (int nt = 0; nt < 4; ++nt) {
            int n0 = nw + nt * 8 + 2 * tg;
            c[nt][0] = s_b[n0]; c[nt][1] = s_b[n0 + 1];
            c[nt][2] = c[nt][0]; c[nt][3] = c[nt][1];
        }

        #pragma unroll
        for (int kk = 0; kk < 8; ++kk) {
            int k0 = kk * 16;
            const __nv_bfloat16* pa = s_act + (mw + g) * STRIDE + k0 + 2 * tg;
            uint32_t a0 = *(const uint32_t*)pa;
            uint32_t a1 = *(const uint32_t*)(pa + 8 * STRIDE);
            uint32_t a2 = *(const uint32_t*)(pa + 8);
            uint32_t a3 = *(const uint32_t*)(pa + 8 * STRIDE + 8);
            #pragma unroll
            for (int nt = 0; nt < 4; ++nt) {
                const __nv_bfloat16* pb = s_w + (nw + nt * 8 + g) * STRIDE + k0 + 2 * tg;
                uint32_t b0 = *(const uint32_t*)pb;
                uint32_t b1 = *(const uint32_t*)(pb + 8);
                mma16816(c[nt][0], c[nt][1], c[nt][2], c[nt][3], a0, a1, a2, a3, b0, b1);
            }
        }

        if (!LAST) {
            #pragma unroll
            for (int nt = 0; nt < 4; ++nt) {
                int n0 = nw + nt * 8 + 2 * tg;
                int m0 = nb + mw + g;
                float v0 = c[nt][0], v1 = c[nt][1], v2 = c[nt][2], v3 = c[nt][3];
                if (RELU) {
                    v0 = fmaxf(v0, 0.f); v1 = fmaxf(v1, 0.f);
                    v2 = fmaxf(v2, 0.f); v3 = fmaxf(v3, 0.f);
                }
                __nv_bfloat162 p0 = __floats2bfloat162_rn(v0, v1);
                __nv_bfloat162 p1 = __floats2bfloat162_rn(v2, v3);
                *(__nv_bfloat162*)(outbf + (size_t)m0 * 64 + n0) = p0;
                *(__nv_bfloat162*)(outbf + (size_t)(m0 + 8) * 64 + n0) = p1;
            }
        } else {
            // logits -> smem (overlay dead weight tile), then fused loss
            __syncthreads();
            float* lf = (float*)s_w;               // [64][41] floats
            #pragma unroll
            for (int nt = 0; nt < 4; ++nt) {
                int n0 = nw + nt * 8 + 2 * tg;
                if (n0 < DOUT_FINAL) {
                    lf[(mw + g) * 41 + n0]         = c[nt][0];
                    lf[(mw + g) * 41 + n0 + 1]     = c[nt][1];
                    lf[(mw + g + 8) * 41 + n0]     = c[nt][2];
                    lf[(mw + g + 8) * 41 + n0 + 1] = c[nt][3];
                }
            }
            __syncthreads();
            if (t < 64) {
                float nll = 0.f, mv = 0.f;
                int gn = nb + t;
                if (__ldg(mask + gn) != 0) {
                    const float* l = lf + t * 41;
                    float mx = l[0];
                    #pragma unroll
                    for (int d = 1; d < DOUT_FINAL; ++d) mx = fmaxf(mx, l[d]);
                    float s = 0.f;
                    #pragma unroll
                    for (int d = 0; d < DOUT_FINAL; ++d) s += expf(l[d] - mx);
                    nll = mx + logf(s) - l[__ldg(y + gn)];
                    mv = 1.f;
                }
                #pragma unroll
                for (int o = 16; o > 0; o >>= 1) {
                    nll += __shfl_down_sync(0xffffffffu, nll, o);
                    mv  += __shfl_down_sync(0xffffffffu, mv, o);
                }
                if ((t & 31) == 0) {
                    atomicAdd(&g_acc[0], nll);
                    atomicAdd(&g_acc[1], mv);
                }
            }
        }
    }
}

__global__ void k_final(float* out) {
    out[0] = g_acc[0] / fmaxf(g_acc[1], 1.f);
}

// ---------------- launcher ----------------
extern "C" void kernel_launch(void* const* d_in, const int* in_sizes, int n_in,
                              void* d_out, int out_size) {
    const float* x   = (const float*)d_in[0];
    const float* Wl0 = (const float*)d_in[1];
    const float* bl0 = (const float*)d_in[2];
    const float* Wr0 = (const float*)d_in[3];
    const float* br0 = (const float*)d_in[4];
    const float* Wl1 = (const float*)d_in[5];
    const float* bl1 = (const float*)d_in[6];
    const float* Wr1 = (const float*)d_in[7];
    const float* br1 = (const float*)d_in[8];
    const float* Wl2 = (const float*)d_in[9];
    const float* bl2 = (const float*)d_in[10];
    const float* Wr2 = (const float*)d_in[11];
    const float* br2 = (const float*)d_in[12];
    const int*   ei  = (const int*)d_in[13];
    const int*   y   = (const int*)d_in[14];
    const int*   msk = (const int*)d_in[15];
    const int* dst = ei;        // edge_index[0]
    const int* src = ei + EE;   // edge_index[1]

    __nv_bfloat16 *bfA, *bfB, *wbf;
    float *bias;
    cudaGetSymbolAddress((void**)&bfA, g_bfA);
    cudaGetSymbolAddress((void**)&bfB, g_bfB);
    cudaGetSymbolAddress((void**)&wbf, g_wbf);
    cudaGetSymbolAddress((void**)&bias, g_bias);

    // preamble: 2 kernels only
    k_zero<<<(NN + 255) / 256, 256>>>(Wl0, bl0, Wr0, br0, Wl1, bl1, Wr1, br1, Wl2, bl2, Wr2, br2);
    k_build<<<1250, 256>>>(dst, src, x);

    const int blocks = NN / 64;   // 1250

    // layer 0: bfA -> bfB
    k_layer<true, false><<<blocks, 256>>>(bfA, wbf, bias, bfB, nullptr, nullptr);
    // layer 1: bfB -> bfA
    k_layer<true, false><<<blocks, 256>>>(bfB, wbf + 64 * 128, bias + 64, bfA, nullptr, nullptr);
    // layer 2: bfA -> loss accumulators (loss fused; unmasked nodes skipped)
    k_layer<false, true><<<blocks, 256>>>(bfA, wbf + 2 * 64 * 128, bias + 128, nullptr, y, msk);

    k_final<<<1, 1>>>((float*)d_out);
}